// round 3
// baseline (speedup 1.0000x reference)
#include <cuda_runtime.h>
#include <cuda_bf16.h>
#include <math.h>

#define N_NODES 50000
#define N_EDGES 512000
#define DIM 64
#define DIM2 128
#define DIM3 192
#define NLAYERS 4

// ---------------- scratch (device globals; no allocation allowed) ----------------
__device__ float g_node[N_NODES * DIM];          // 12.8 MB
__device__ float g_edge[(size_t)N_EDGES * DIM];  // 131 MB
__device__ float g_agg[N_NODES * DIM];           // 12.8 MB
__device__ float g_m[(size_t)N_EDGES * DIM3];    // 393 MB

// ---------------- encoders ----------------
__global__ void encode_node_kernel(const int* __restrict__ x,
                                   const float* __restrict__ atom_emb) {
    int idx = blockIdx.x * blockDim.x + threadIdx.x;
    if (idx >= N_NODES * DIM) return;
    int n = idx >> 6, d = idx & 63;
    float acc = 0.f;
#pragma unroll
    for (int f = 0; f < 9; f++) {
        int xv = x[n * 9 + f];
        acc += atom_emb[((size_t)(f * 119 + xv)) * DIM + d];
    }
    g_node[idx] = acc;
}

__global__ void encode_edge_kernel(const int* __restrict__ edge_attr,
                                   const float* __restrict__ bond_emb) {
    long idx = (long)blockIdx.x * blockDim.x + threadIdx.x;
    if (idx >= (long)N_EDGES * DIM) return;
    int e = (int)(idx >> 6), d = (int)(idx & 63);
    float acc = 0.f;
#pragma unroll
    for (int f = 0; f < 3; f++) {
        int av = edge_attr[e * 3 + f];
        acc += bond_emb[(f * 6 + av) * DIM + d];
    }
    g_edge[idx] = acc;
}

// ---------------- zero agg ----------------
__global__ void zero_agg_kernel() {
    int idx = blockIdx.x * blockDim.x + threadIdx.x;
    if (idx < N_NODES * DIM) g_agg[idx] = 0.f;
}

// ---------------- message + scatter: agg[dst] += relu(node[src] + edge) ----------------
__global__ void scatter_kernel(const int* __restrict__ ei) {
    long idx = (long)blockIdx.x * blockDim.x + threadIdx.x;
    if (idx >= (long)N_EDGES * 16) return;
    int e = (int)(idx >> 4);
    int q = (int)(idx & 15) * 4;
    int s = ei[e];
    int d = ei[N_EDGES + e];
    float4 a = *(const float4*)&g_node[(size_t)s * DIM + q];
    float4 b = *(const float4*)&g_edge[(size_t)e * DIM + q];
    float4 m;
    m.x = fmaxf(a.x + b.x, 0.f);
    m.y = fmaxf(a.y + b.y, 0.f);
    m.z = fmaxf(a.z + b.z, 0.f);
    m.w = fmaxf(a.w + b.w, 0.f);
    float* p = &g_agg[(size_t)d * DIM + q];
    atomicAdd(p + 0, m.x);
    atomicAdd(p + 1, m.y);
    atomicAdd(p + 2, m.z);
    atomicAdd(p + 3, m.w);
}

// ---------------- node MLP + LN + relu + residual ----------------
__global__ void node_mlp_kernel(const float* __restrict__ W1, const float* __restrict__ b1,
                                const float* __restrict__ W2, const float* __restrict__ b2,
                                const float* __restrict__ lng, const float* __restrict__ lnb,
                                const float* __restrict__ eps_arr, int l) {
    extern __shared__ float smem[];
    float* sW1 = smem;            // 64*128
    float* sW2 = smem + 64 * 128; // 128*64
    __shared__ float s_in[DIM];
    __shared__ float s_hid[DIM2];
    __shared__ float s_out[DIM];
    __shared__ float s_red[4];
    int t = threadIdx.x;
    for (int i = t; i < 64 * 128; i += 128) sW1[i] = W1[i];
    for (int i = t; i < 128 * 64; i += 128) sW2[i] = W2[i];
    float ep = 1.f + eps_arr[l];
    __syncthreads();
    for (int n = blockIdx.x; n < N_NODES; n += gridDim.x) {
        if (t < 64) s_in[t] = ep * g_node[n * DIM + t] + g_agg[n * DIM + t];
        __syncthreads();
        float acc = b1[t];
#pragma unroll
        for (int k = 0; k < 64; k++) acc += s_in[k] * sW1[k * 128 + t];
        s_hid[t] = fmaxf(acc, 0.f);
        __syncthreads();
        if (t < 64) {
            float a2 = b2[t];
#pragma unroll
            for (int k = 0; k < 128; k++) a2 += s_hid[k] * sW2[k * 64 + t];
            s_out[t] = a2;
            float s1 = a2, s2 = a2 * a2;
#pragma unroll
            for (int o = 16; o; o >>= 1) {
                s1 += __shfl_xor_sync(0xffffffffu, s1, o);
                s2 += __shfl_xor_sync(0xffffffffu, s2, o);
            }
            if ((t & 31) == 0) {
                s_red[t >> 5] = s1;
                s_red[2 + (t >> 5)] = s2;
            }
        }
        __syncthreads();
        if (t < 64) {
            float mean = (s_red[0] + s_red[1]) * (1.f / 64.f);
            float var = (s_red[2] + s_red[3]) * (1.f / 64.f) - mean * mean;
            float inv = rsqrtf(var + 1e-5f);
            float hv = (s_out[t] - mean) * inv * lng[t] + lnb[t];
            g_node[n * DIM + t] = fmaxf(hv, 0.f) + g_node[n * DIM + t];
        }
        __syncthreads();
    }
}

// ---------------- fused gather-GEMM1 + LN + relu ----------------
// m = relu(LN([node[src]|node[dst]|edge] @ Wu1 + bu1))
// BM=128, BN=192 (full width), K=192, 256 threads, 8x12 per-thread tile.
// LN reduction across the 16 lanes sharing a row (shfl within half-warp).
__global__ void gemm1_ln_kernel(const int* __restrict__ ei,
                                const float* __restrict__ B,
                                const float* __restrict__ bias,
                                const float* __restrict__ ug,
                                const float* __restrict__ ub,
                                float* __restrict__ C) {
    __shared__ float As[16][128];
    __shared__ float Bs[16][192];
    __shared__ int s_src[128];
    __shared__ int s_dst[128];
    __shared__ float s_bias[192], s_ug[192], s_ub[192];
    int t = threadIdx.x;
    int m0 = blockIdx.x * 128;
    if (t < 128) s_src[t] = ei[m0 + t];
    else s_dst[t - 128] = ei[N_EDGES + m0 + (t - 128)];
    if (t < 192) {
        s_bias[t] = bias[t];
        s_ug[t] = ug[t];
        s_ub[t] = ub[t];
    }
    int tm = (t >> 4) * 8;      // 0..120
    int tn = (t & 15) * 12;     // 0..180
    int arow = t >> 2;          // 0..63 (two halves)
    int acol = (t & 3) * 4;     // 0,4,8,12
    int brow = t >> 4;          // 0..15
    int bcol = (t & 15) * 12;   // 0..180
    float acc[8][12];
#pragma unroll
    for (int i = 0; i < 8; i++)
#pragma unroll
        for (int j = 0; j < 12; j++) acc[i][j] = 0.f;
    __syncthreads();
#pragma unroll
    for (int k0 = 0; k0 < DIM3; k0 += 16) {
        int seg = k0 >> 6;
        int off = (k0 & 63) + acol;
        float4 a0, a1;
        if (seg == 0) {
            a0 = *(const float4*)&g_node[(size_t)s_src[arow] * DIM + off];
            a1 = *(const float4*)&g_node[(size_t)s_src[arow + 64] * DIM + off];
        } else if (seg == 1) {
            a0 = *(const float4*)&g_node[(size_t)s_dst[arow] * DIM + off];
            a1 = *(const float4*)&g_node[(size_t)s_dst[arow + 64] * DIM + off];
        } else {
            a0 = *(const float4*)&g_edge[(size_t)(m0 + arow) * DIM + off];
            a1 = *(const float4*)&g_edge[(size_t)(m0 + arow + 64) * DIM + off];
        }
        As[acol + 0][arow] = a0.x; As[acol + 1][arow] = a0.y;
        As[acol + 2][arow] = a0.z; As[acol + 3][arow] = a0.w;
        As[acol + 0][arow + 64] = a1.x; As[acol + 1][arow + 64] = a1.y;
        As[acol + 2][arow + 64] = a1.z; As[acol + 3][arow + 64] = a1.w;
        const float* brp = &B[(size_t)(k0 + brow) * DIM3 + bcol];
        *(float4*)&Bs[brow][bcol + 0] = *(const float4*)(brp + 0);
        *(float4*)&Bs[brow][bcol + 4] = *(const float4*)(brp + 4);
        *(float4*)&Bs[brow][bcol + 8] = *(const float4*)(brp + 8);
        __syncthreads();
#pragma unroll
        for (int k = 0; k < 16; k++) {
            float ra[8], rb[12];
#pragma unroll
            for (int i = 0; i < 8; i += 4) *(float4*)&ra[i] = *(const float4*)&As[k][tm + i];
#pragma unroll
            for (int j = 0; j < 12; j += 4) *(float4*)&rb[j] = *(const float4*)&Bs[k][tn + j];
#pragma unroll
            for (int i = 0; i < 8; i++)
#pragma unroll
                for (int j = 0; j < 12; j++) acc[i][j] += ra[i] * rb[j];
        }
        __syncthreads();
    }
    // epilogue: bias + LN(192) + relu, row-wise; 16 lanes (same half-warp) share a row
#pragma unroll
    for (int i = 0; i < 8; i++) {
        size_t row = (size_t)(m0 + tm + i);
        float s1 = 0.f, s2 = 0.f;
#pragma unroll
        for (int j = 0; j < 12; j++) {
            float v = acc[i][j] + s_bias[tn + j];
            acc[i][j] = v;
            s1 += v;
            s2 += v * v;
        }
#pragma unroll
        for (int o = 1; o < 16; o <<= 1) {
            s1 += __shfl_xor_sync(0xffffffffu, s1, o);
            s2 += __shfl_xor_sync(0xffffffffu, s2, o);
        }
        float mean = s1 * (1.f / 192.f);
        float var = s2 * (1.f / 192.f) - mean * mean;
        float inv = rsqrtf(var + 1e-5f);
        float* cp = &C[row * DIM3 + tn];
#pragma unroll
        for (int j = 0; j < 12; j++) {
            float r = (acc[i][j] - mean) * inv * s_ug[tn + j] + s_ub[tn + j];
            cp[j] = fmaxf(r, 0.f);
        }
    }
}

// ---------------- GEMM2: C[M,64] = A[M,192]@B[192,64] + bias + resid ----------------
__global__ void gemm2_kernel(const float* __restrict__ A, const float* __restrict__ B,
                             const float* __restrict__ bias, const float* __restrict__ resid,
                             float* __restrict__ C) {
    __shared__ float As[16][128];
    __shared__ float Bs[16][64];
    int t = threadIdx.x;
    int m0 = blockIdx.x * 128;
    int tm = (t >> 4) * 8;
    int tn = (t & 15) * 4;
    int arow = t >> 2;
    int acol = (t & 3) * 4;
    int brow = t >> 4;
    int bcol = (t & 15) * 4;
    float acc[8][4];
#pragma unroll
    for (int i = 0; i < 8; i++)
#pragma unroll
        for (int j = 0; j < 4; j++) acc[i][j] = 0.f;
#pragma unroll
    for (int k0 = 0; k0 < DIM3; k0 += 16) {
        float4 a0 = *(const float4*)&A[(size_t)(m0 + arow) * DIM3 + k0 + acol];
        float4 a1 = *(const float4*)&A[(size_t)(m0 + arow + 64) * DIM3 + k0 + acol];
        As[acol + 0][arow] = a0.x; As[acol + 1][arow] = a0.y;
        As[acol + 2][arow] = a0.z; As[acol + 3][arow] = a0.w;
        As[acol + 0][arow + 64] = a1.x; As[acol + 1][arow + 64] = a1.y;
        As[acol + 2][arow + 64] = a1.z; As[acol + 3][arow + 64] = a1.w;
        *(float4*)&Bs[brow][bcol] = *(const float4*)&B[(size_t)(k0 + brow) * DIM + bcol];
        __syncthreads();
#pragma unroll
        for (int k = 0; k < 16; k++) {
            float ra[8], rb[4];
#pragma unroll
            for (int i = 0; i < 8; i++) ra[i] = As[k][tm + i];
#pragma unroll
            for (int j = 0; j < 4; j++) rb[j] = Bs[k][tn + j];
#pragma unroll
            for (int i = 0; i < 8; i++)
#pragma unroll
                for (int j = 0; j < 4; j++) acc[i][j] += ra[i] * rb[j];
        }
        __syncthreads();
    }
#pragma unroll
    for (int i = 0; i < 8; i++) {
        size_t row = (size_t)(m0 + tm + i);
#pragma unroll
        for (int j = 0; j < 4; j++) {
            int col = tn + j;
            C[row * DIM + col] = acc[i][j] + bias[col] + resid[row * DIM + col];
        }
    }
}

// ---------------- output copy: node part ----------------
__global__ void copy_node_kernel(float* __restrict__ out) {
    int idx = blockIdx.x * blockDim.x + threadIdx.x;
    if (idx < N_NODES * DIM) out[idx] = g_node[idx];
}

extern "C" void kernel_launch(void* const* d_in, const int* in_sizes, int n_in,
                              void* d_out, int out_size) {
    const int* x = (const int*)d_in[0];
    const int* edge_attr = (const int*)d_in[1];
    const int* edge_index = (const int*)d_in[2];
    const float* atom_emb = (const float*)d_in[3];
    const float* bond_emb = (const float*)d_in[4];
    const float* eps = (const float*)d_in[5];
    const float* W1 = (const float*)d_in[6];
    const float* b1 = (const float*)d_in[7];
    const float* W2 = (const float*)d_in[8];
    const float* b2 = (const float*)d_in[9];
    const float* ln_g = (const float*)d_in[10];
    const float* ln_b = (const float*)d_in[11];
    const float* Wu1 = (const float*)d_in[12];
    const float* bu1 = (const float*)d_in[13];
    const float* ug = (const float*)d_in[14];
    const float* ub = (const float*)d_in[15];
    const float* Wu2 = (const float*)d_in[16];
    const float* bu2 = (const float*)d_in[17];
    float* out = (float*)d_out;

    float* g_edge_p = nullptr;
    cudaGetSymbolAddress((void**)&g_edge_p, g_edge);
    float* g_m_p = nullptr;
    cudaGetSymbolAddress((void**)&g_m_p, g_m);

    cudaFuncSetAttribute(node_mlp_kernel, cudaFuncAttributeMaxDynamicSharedMemorySize, 65536);

    encode_node_kernel<<<(N_NODES * DIM + 255) / 256, 256>>>(x, atom_emb);
    encode_edge_kernel<<<(int)(((long)N_EDGES * DIM + 255) / 256), 256>>>(edge_attr, bond_emb);

    for (int l = 0; l < NLAYERS; l++) {
        zero_agg_kernel<<<(N_NODES * DIM + 255) / 256, 256>>>();
        scatter_kernel<<<(int)(((long)N_EDGES * 16 + 255) / 256), 256>>>(edge_index);
        node_mlp_kernel<<<444, 128, 65536>>>(
            W1 + (size_t)l * 64 * 128, b1 + l * 128,
            W2 + (size_t)l * 128 * 64, b2 + l * 64,
            ln_g + l * 64, ln_b + l * 64, eps, l);
        // m = relu(LN([node[src]|node[dst]|edge] @ Wu1 + bu1))   [E,192]
        gemm1_ln_kernel<<<N_EDGES / 128, 256>>>(edge_index,
                                                Wu1 + (size_t)l * DIM3 * DIM3,
                                                bu1 + l * DIM3,
                                                ug + l * DIM3, ub + l * DIM3,
                                                g_m_p);
        // edge = m @ Wu2 + bu2 + edge   [E,64]
        {
            float* edge_out = (l == NLAYERS - 1) ? (out + (size_t)N_NODES * DIM) : g_edge_p;
            gemm2_kernel<<<N_EDGES / 128, 256>>>(g_m_p, Wu2 + (size_t)l * DIM3 * DIM,
                                                 bu2 + l * DIM, g_edge_p, edge_out);
        }
    }

    copy_node_kernel<<<(N_NODES * DIM + 255) / 256, 256>>>(out);
}

// round 5
// speedup vs baseline: 1.6528x; 1.6528x over previous
#include <cuda_runtime.h>
#include <cuda_bf16.h>
#include <cstdint>
#include <math.h>
#include <string.h>

#define N_NODES 50000
#define N_EDGES 512000
#define DIM 64
#define DIM2 128
#define DIM3 192
#define NLAYERS 4

// ---------------- scratch (device globals; no allocation allowed) ----------------
__device__ float g_node[N_NODES * DIM];
__device__ float g_edge[(size_t)N_EDGES * DIM];
__device__ float g_agg[N_NODES * DIM];
// split-bf16 weights, K-major [N][K], per layer
__device__ __nv_bfloat16 g_b1hi[NLAYERS * DIM3 * DIM3];
__device__ __nv_bfloat16 g_b1lo[NLAYERS * DIM3 * DIM3];
__device__ __nv_bfloat16 g_b2hi[NLAYERS * DIM * DIM3];
__device__ __nv_bfloat16 g_b2lo[NLAYERS * DIM * DIM3];

// ================= helpers =================
__device__ __forceinline__ uint32_t smem_u32(const void* p) {
    uint32_t a;
    asm("{ .reg .u64 t; cvta.to.shared.u64 t, %1; cvt.u32.u64 %0, t; }" : "=r"(a) : "l"(p));
    return a;
}
__device__ __forceinline__ uint32_t pack_bf16(float a, float b) {
    __nv_bfloat162 h = __floats2bfloat162_rn(a, b);
    uint32_t u;
    memcpy(&u, &h, 4);
    return u;
}
__device__ __forceinline__ void ldm4(uint32_t* r, uint32_t addr) {
    asm volatile("ldmatrix.sync.aligned.m8n8.x4.shared.b16 {%0,%1,%2,%3}, [%4];"
                 : "=r"(r[0]), "=r"(r[1]), "=r"(r[2]), "=r"(r[3]) : "r"(addr));
}
__device__ __forceinline__ void ldm2(uint32_t* r, uint32_t addr) {
    asm volatile("ldmatrix.sync.aligned.m8n8.x2.shared.b16 {%0,%1}, [%2];"
                 : "=r"(r[0]), "=r"(r[1]) : "r"(addr));
}
__device__ __forceinline__ void mma16816(float* c, const uint32_t* a, const uint32_t* b) {
    asm volatile(
        "mma.sync.aligned.m16n8k16.row.col.f32.bf16.bf16.f32 "
        "{%0,%1,%2,%3}, {%4,%5,%6,%7}, {%8,%9}, {%0,%1,%2,%3};"
        : "+f"(c[0]), "+f"(c[1]), "+f"(c[2]), "+f"(c[3])
        : "r"(a[0]), "r"(a[1]), "r"(a[2]), "r"(a[3]), "r"(b[0]), "r"(b[1]));
}

// ---------------- encoders ----------------
__global__ void encode_node_kernel(const int* __restrict__ x,
                                   const float* __restrict__ atom_emb) {
    int idx = blockIdx.x * blockDim.x + threadIdx.x;
    if (idx >= N_NODES * DIM) return;
    int n = idx >> 6, d = idx & 63;
    float acc = 0.f;
#pragma unroll
    for (int f = 0; f < 9; f++) {
        int xv = x[n * 9 + f];
        acc += atom_emb[((size_t)(f * 119 + xv)) * DIM + d];
    }
    g_node[idx] = acc;
}

__global__ void encode_edge_kernel(const int* __restrict__ edge_attr,
                                   const float* __restrict__ bond_emb) {
    long idx = (long)blockIdx.x * blockDim.x + threadIdx.x;
    if (idx >= (long)N_EDGES * DIM) return;
    int e = (int)(idx >> 6), d = (int)(idx & 63);
    float acc = 0.f;
#pragma unroll
    for (int f = 0; f < 3; f++) {
        int av = edge_attr[e * 3 + f];
        acc += bond_emb[(f * 6 + av) * DIM + d];
    }
    g_edge[idx] = acc;
}

// ---------------- weight preprocessing: split fp32 -> bf16 hi/lo, K-major [N][K] ----------------
__global__ void prep_weights_kernel(const float* __restrict__ Wu1, const float* __restrict__ Wu2) {
    int idx = blockIdx.x * blockDim.x + threadIdx.x;
    const int n1 = NLAYERS * DIM3 * DIM3;
    if (idx < n1) {
        int l = idx / (DIM3 * DIM3);
        int r = idx % (DIM3 * DIM3);
        int n = r / DIM3, k = r % DIM3;
        float v = Wu1[(size_t)l * DIM3 * DIM3 + (size_t)k * DIM3 + n];
        __nv_bfloat16 h = __float2bfloat16(v);
        g_b1hi[idx] = h;
        g_b1lo[idx] = __float2bfloat16(v - __bfloat162float(h));
    } else if (idx < n1 + NLAYERS * DIM * DIM3) {
        int i2 = idx - n1;
        int l = i2 / (DIM * DIM3);
        int r = i2 % (DIM * DIM3);
        int n = r / DIM3, k = r % DIM3;
        float v = Wu2[(size_t)l * DIM3 * DIM + (size_t)k * DIM + n];
        __nv_bfloat16 h = __float2bfloat16(v);
        g_b2hi[i2] = h;
        g_b2lo[i2] = __float2bfloat16(v - __bfloat162float(h));
    }
}

// ---------------- zero agg ----------------
__global__ void zero_agg_kernel() {
    int idx = blockIdx.x * blockDim.x + threadIdx.x;
    if (idx < N_NODES * DIM) g_agg[idx] = 0.f;
}

// ---------------- scatter: agg[dst] += relu(node[src] + edge) ----------------
__global__ void scatter_kernel(const int* __restrict__ ei) {
    long idx = (long)blockIdx.x * blockDim.x + threadIdx.x;
    if (idx >= (long)N_EDGES * 16) return;
    int e = (int)(idx >> 4);
    int q = (int)(idx & 15) * 4;
    int s = ei[e];
    int d = ei[N_EDGES + e];
    float4 a = *(const float4*)&g_node[(size_t)s * DIM + q];
    float4 b = *(const float4*)&g_edge[(size_t)e * DIM + q];
    float4 m;
    m.x = fmaxf(a.x + b.x, 0.f);
    m.y = fmaxf(a.y + b.y, 0.f);
    m.z = fmaxf(a.z + b.z, 0.f);
    m.w = fmaxf(a.w + b.w, 0.f);
    float* p = &g_agg[(size_t)d * DIM + q];
    atomicAdd(p + 0, m.x);
    atomicAdd(p + 1, m.y);
    atomicAdd(p + 2, m.z);
    atomicAdd(p + 3, m.w);
}

// ---------------- node MLP + LN + relu + residual ----------------
__global__ void node_mlp_kernel(const float* __restrict__ W1, const float* __restrict__ b1,
                                const float* __restrict__ W2, const float* __restrict__ b2,
                                const float* __restrict__ lng, const float* __restrict__ lnb,
                                const float* __restrict__ eps_arr, int l) {
    extern __shared__ float smemf[];
    float* sW1 = smemf;
    float* sW2 = smemf + 64 * 128;
    __shared__ float s_in[DIM];
    __shared__ float s_hid[DIM2];
    __shared__ float s_out[DIM];
    __shared__ float s_red[4];
    int t = threadIdx.x;
    for (int i = t; i < 64 * 128; i += 128) sW1[i] = W1[i];
    for (int i = t; i < 128 * 64; i += 128) sW2[i] = W2[i];
    float ep = 1.f + eps_arr[l];
    __syncthreads();
    for (int n = blockIdx.x; n < N_NODES; n += gridDim.x) {
        if (t < 64) s_in[t] = ep * g_node[n * DIM + t] + g_agg[n * DIM + t];
        __syncthreads();
        float acc = b1[t];
#pragma unroll
        for (int k = 0; k < 64; k++) acc += s_in[k] * sW1[k * 128 + t];
        s_hid[t] = fmaxf(acc, 0.f);
        __syncthreads();
        if (t < 64) {
            float a2 = b2[t];
#pragma unroll
            for (int k = 0; k < 128; k++) a2 += s_hid[k] * sW2[k * 64 + t];
            s_out[t] = a2;
            float s1 = a2, s2 = a2 * a2;
#pragma unroll
            for (int o = 16; o; o >>= 1) {
                s1 += __shfl_xor_sync(0xffffffffu, s1, o);
                s2 += __shfl_xor_sync(0xffffffffu, s2, o);
            }
            if ((t & 31) == 0) {
                s_red[t >> 5] = s1;
                s_red[2 + (t >> 5)] = s2;
            }
        }
        __syncthreads();
        if (t < 64) {
            float mean = (s_red[0] + s_red[1]) * (1.f / 64.f);
            float var = (s_red[2] + s_red[3]) * (1.f / 64.f) - mean * mean;
            float inv = rsqrtf(var + 1e-5f);
            float hv = (s_out[t] - mean) * inv * lng[t] + lnb[t];
            g_node[n * DIM + t] = fmaxf(hv, 0.f) + g_node[n * DIM + t];
        }
        __syncthreads();
    }
}

// ================= fused edge layer: mma.sync split-bf16 =================
// SMEM layout (dynamic), strides: A/B1 chunks 72 bf16 = 144B; m/B2 rows 200 bf16 = 400B
#define OFF_A_HI 0
#define OFF_A_LO 18432
#define OFF_B_HI 36864
#define OFF_B_LO 64512
#define OFF_M_HI 92160
#define OFF_M_LO 143360
#define OFF_B2_HI OFF_A_HI
#define OFF_B2_LO OFF_B_HI
#define SMEM_EDGE 194560

__global__ void __launch_bounds__(256, 1)
edge_layer_kernel(const int* __restrict__ ei,
                  const float* __restrict__ bu1, const float* __restrict__ ug,
                  const float* __restrict__ ub, const float* __restrict__ bu2,
                  int l, float* edge_out) {
    extern __shared__ char sm[];
    __shared__ float s_bias[DIM3], s_g[DIM3], s_bn[DIM3], s_b2[DIM];
    __shared__ float s_part[2][128][2];
    int t = threadIdx.x, lane = t & 31, wid = t >> 5;
    int warp_m = wid >> 1, warp_n = wid & 1;
    int m0 = blockIdx.x * 128;
    uint32_t sb = smem_u32(sm);

    for (int i = t; i < DIM3; i += 256) {
        s_bias[i] = bu1[i];
        s_g[i] = ug[i];
        s_bn[i] = ub[i];
    }
    if (t < DIM) s_b2[t] = bu2[t];

    int row = t >> 1, half = t & 1;
    int src_i = ei[m0 + row];
    int dst_i = ei[N_EDGES + m0 + row];

    const __nv_bfloat16* w1hi = g_b1hi + (size_t)l * DIM3 * DIM3;
    const __nv_bfloat16* w1lo = g_b1lo + (size_t)l * DIM3 * DIM3;
    const __nv_bfloat16* w2hi = g_b2hi + (size_t)l * DIM * DIM3;
    const __nv_bfloat16* w2lo = g_b2lo + (size_t)l * DIM * DIM3;

    float acc[2][12][4];
#pragma unroll
    for (int i = 0; i < 2; i++)
#pragma unroll
        for (int j = 0; j < 12; j++)
#pragma unroll
            for (int q = 0; q < 4; q++) acc[i][j][q] = 0.f;

    int l4 = lane & 15;
    uint32_t a_hi_b = sb + OFF_A_HI + (uint32_t)(warp_m * 32 + l4) * 144 + (lane >> 4) * 16;
    uint32_t a_lo_b = sb + OFF_A_LO + (uint32_t)(warp_m * 32 + l4) * 144 + (lane >> 4) * 16;
    uint32_t b_hi_b = sb + OFF_B_HI + (uint32_t)(warp_n * 96 + (l4 & 7)) * 144 + (l4 >> 3) * 16;
    uint32_t b_lo_b = sb + OFF_B_LO + (uint32_t)(warp_n * 96 + (l4 & 7)) * 144 + (l4 >> 3) * 16;

    for (int c = 0; c < 3; c++) {
        __syncthreads();
        // ---- gather + split A chunk (128 rows x 64 K) ----
        const float* ap;
        if (c == 0) ap = g_node + (size_t)src_i * DIM;
        else if (c == 1) ap = g_node + (size_t)dst_i * DIM;
        else ap = g_edge + (size_t)(m0 + row) * DIM;
        ap += half * 32;
        uint32_t wb = (uint32_t)row * 144 + half * 64;
#pragma unroll
        for (int q = 0; q < 8; q++) {
            float4 f = ((const float4*)ap)[q];
            __nv_bfloat16 hx = __float2bfloat16(f.x), hy = __float2bfloat16(f.y);
            __nv_bfloat16 hz = __float2bfloat16(f.z), hw = __float2bfloat16(f.w);
            uint2 hv, lv;
            hv.x = pack_bf16(f.x, f.y);
            hv.y = pack_bf16(f.z, f.w);
            lv.x = pack_bf16(f.x - __bfloat162float(hx), f.y - __bfloat162float(hy));
            lv.y = pack_bf16(f.z - __bfloat162float(hz), f.w - __bfloat162float(hw));
            *(uint2*)(sm + OFF_A_HI + wb + q * 8) = hv;
            *(uint2*)(sm + OFF_A_LO + wb + q * 8) = lv;
        }
        // ---- load B1 chunk (192 N-rows x 64 K bf16) ----
        if (t < DIM3) {
            const uint4* p4h = (const uint4*)(w1hi + (size_t)t * DIM3 + c * 64);
            const uint4* p4l = (const uint4*)(w1lo + (size_t)t * DIM3 + c * 64);
            uint32_t nb = (uint32_t)t * 144;
#pragma unroll
            for (int q = 0; q < 8; q++) {
                *(uint4*)(sm + OFF_B_HI + nb + q * 16) = p4h[q];
                *(uint4*)(sm + OFF_B_LO + nb + q * 16) = p4l[q];
            }
        }
        __syncthreads();
        // ---- mma over 4 k-steps ----
#pragma unroll
        for (int ks = 0; ks < 4; ks++) {
            uint32_t ah[2][4], al[2][4];
            ldm4(ah[0], a_hi_b + ks * 32);
            ldm4(ah[1], a_hi_b + 16 * 144 + ks * 32);
            ldm4(al[0], a_lo_b + ks * 32);
            ldm4(al[1], a_lo_b + 16 * 144 + ks * 32);
#pragma unroll
            for (int nt = 0; nt < 12; nt++) {
                uint32_t bh[2], bl[2];
                ldm2(bh, b_hi_b + nt * (8 * 144) + ks * 32);
                ldm2(bl, b_lo_b + nt * (8 * 144) + ks * 32);
#pragma unroll
                for (int mt = 0; mt < 2; mt++) {
                    mma16816(acc[mt][nt], ah[mt], bh);
                    mma16816(acc[mt][nt], al[mt], bh);
                    mma16816(acc[mt][nt], ah[mt], bl);
                }
            }
        }
    }
    __syncthreads();
    // ---- load B2 into freed stage area ----
    {
        int part = t >> 6, n = t & 63;
        if (part < 2) {
            const uint4* p4 = (const uint4*)((part ? w2lo : w2hi) + (size_t)n * DIM3);
            uint32_t nb = (uint32_t)n * 400;
            int off = part ? OFF_B2_LO : OFF_B2_HI;
#pragma unroll
            for (int q = 0; q < 24; q++) *(uint4*)(sm + off + nb + q * 16) = p4[q];
        }
    }
    // ---- bias + row stats ----
    float p1[4] = {0.f, 0.f, 0.f, 0.f}, p2[4] = {0.f, 0.f, 0.f, 0.f};
    int cb = warp_n * 96 + (lane & 3) * 2;
#pragma unroll
    for (int mt = 0; mt < 2; mt++)
#pragma unroll
        for (int nt = 0; nt < 12; nt++) {
            int col = cb + nt * 8;
            float* a = acc[mt][nt];
            a[0] += s_bias[col];
            a[1] += s_bias[col + 1];
            a[2] += s_bias[col];
            a[3] += s_bias[col + 1];
            p1[mt * 2] += a[0] + a[1];
            p2[mt * 2] += a[0] * a[0] + a[1] * a[1];
            p1[mt * 2 + 1] += a[2] + a[3];
            p2[mt * 2 + 1] += a[2] * a[2] + a[3] * a[3];
        }
#pragma unroll
    for (int i = 0; i < 4; i++) {
        p1[i] += __shfl_xor_sync(0xffffffffu, p1[i], 1);
        p1[i] += __shfl_xor_sync(0xffffffffu, p1[i], 2);
        p2[i] += __shfl_xor_sync(0xffffffffu, p2[i], 1);
        p2[i] += __shfl_xor_sync(0xffffffffu, p2[i], 2);
    }
    if ((lane & 3) == 0) {
#pragma unroll
        for (int mt = 0; mt < 2; mt++) {
            int r = warp_m * 32 + mt * 16 + (lane >> 2);
            s_part[warp_n][r][0] = p1[mt * 2];
            s_part[warp_n][r][1] = p2[mt * 2];
            s_part[warp_n][r + 8][0] = p1[mt * 2 + 1];
            s_part[warp_n][r + 8][1] = p2[mt * 2 + 1];
        }
    }
    __syncthreads();
    // ---- LN + relu + split -> sM ----
#pragma unroll
    for (int mt = 0; mt < 2; mt++) {
        int r0 = warp_m * 32 + mt * 16 + (lane >> 2);
        int r1 = r0 + 8;
        float s1a = s_part[0][r0][0] + s_part[1][r0][0];
        float s2a = s_part[0][r0][1] + s_part[1][r0][1];
        float mean0 = s1a * (1.f / 192.f);
        float inv0 = rsqrtf(s2a * (1.f / 192.f) - mean0 * mean0 + 1e-5f);
        float s1b = s_part[0][r1][0] + s_part[1][r1][0];
        float s2b = s_part[0][r1][1] + s_part[1][r1][1];
        float mean1 = s1b * (1.f / 192.f);
        float inv1 = rsqrtf(s2b * (1.f / 192.f) - mean1 * mean1 + 1e-5f);
        uint32_t rb0 = (uint32_t)r0 * 400, rb1 = (uint32_t)r1 * 400;
#pragma unroll
        for (int nt = 0; nt < 12; nt++) {
            int col = cb + nt * 8;
            float* a = acc[mt][nt];
            float v0 = fmaxf((a[0] - mean0) * inv0 * s_g[col] + s_bn[col], 0.f);
            float v1 = fmaxf((a[1] - mean0) * inv0 * s_g[col + 1] + s_bn[col + 1], 0.f);
            float v2 = fmaxf((a[2] - mean1) * inv1 * s_g[col] + s_bn[col], 0.f);
            float v3 = fmaxf((a[3] - mean1) * inv1 * s_g[col + 1] + s_bn[col + 1], 0.f);
            __nv_bfloat16 h0 = __float2bfloat16(v0), h1 = __float2bfloat16(v1);
            __nv_bfloat16 h2 = __float2bfloat16(v2), h3 = __float2bfloat16(v3);
            uint32_t colb = (uint32_t)col * 2;
            *(uint32_t*)(sm + OFF_M_HI + rb0 + colb) = pack_bf16(v0, v1);
            *(uint32_t*)(sm + OFF_M_LO + rb0 + colb) =
                pack_bf16(v0 - __bfloat162float(h0), v1 - __bfloat162float(h1));
            *(uint32_t*)(sm + OFF_M_HI + rb1 + colb) = pack_bf16(v2, v3);
            *(uint32_t*)(sm + OFF_M_LO + rb1 + colb) =
                pack_bf16(v2 - __bfloat162float(h2), v3 - __bfloat162float(h3));
        }
    }
    __syncthreads();
    // ---- GEMM2: [128x192] @ [192x64] ----
    float acc2[2][4][4];
#pragma unroll
    for (int i = 0; i < 2; i++)
#pragma unroll
        for (int j = 0; j < 4; j++)
#pragma unroll
            for (int q = 0; q < 4; q++) acc2[i][j][q] = 0.f;
    uint32_t a2h = sb + OFF_M_HI + (uint32_t)(warp_m * 32 + l4) * 400 + (lane >> 4) * 16;
    uint32_t a2l = sb + OFF_M_LO + (uint32_t)(warp_m * 32 + l4) * 400 + (lane >> 4) * 16;
    uint32_t b2h = sb + OFF_B2_HI + (uint32_t)(warp_n * 32 + (l4 & 7)) * 400 + (l4 >> 3) * 16;
    uint32_t b2l = sb + OFF_B2_LO + (uint32_t)(warp_n * 32 + (l4 & 7)) * 400 + (l4 >> 3) * 16;
#pragma unroll
    for (int kt = 0; kt < 12; kt++) {
        uint32_t ah[2][4], al[2][4];
        ldm4(ah[0], a2h + kt * 32);
        ldm4(ah[1], a2h + 16 * 400 + kt * 32);
        ldm4(al[0], a2l + kt * 32);
        ldm4(al[1], a2l + 16 * 400 + kt * 32);
#pragma unroll
        for (int nt = 0; nt < 4; nt++) {
            uint32_t bh[2], bl[2];
            ldm2(bh, b2h + nt * (8 * 400) + kt * 32);
            ldm2(bl, b2l + nt * (8 * 400) + kt * 32);
#pragma unroll
            for (int mt = 0; mt < 2; mt++) {
                mma16816(acc2[mt][nt], ah[mt], bh);
                mma16816(acc2[mt][nt], al[mt], bh);
                mma16816(acc2[mt][nt], ah[mt], bl);
            }
        }
    }
    // ---- writeback: + bias + residual ----
    int cb2 = warp_n * 32 + (lane & 3) * 2;
#pragma unroll
    for (int mt = 0; mt < 2; mt++) {
        size_t r0 = (size_t)(m0 + warp_m * 32 + mt * 16 + (lane >> 2));
        size_t r1 = r0 + 8;
#pragma unroll
        for (int nt = 0; nt < 4; nt++) {
            int col = cb2 + nt * 8;
            float* a = acc2[mt][nt];
            edge_out[r0 * DIM + col] = a[0] + s_b2[col] + g_edge[r0 * DIM + col];
            edge_out[r0 * DIM + col + 1] = a[1] + s_b2[col + 1] + g_edge[r0 * DIM + col + 1];
            edge_out[r1 * DIM + col] = a[2] + s_b2[col] + g_edge[r1 * DIM + col];
            edge_out[r1 * DIM + col + 1] = a[3] + s_b2[col + 1] + g_edge[r1 * DIM + col + 1];
        }
    }
}

// ---------------- output copy: node part ----------------
__global__ void copy_node_kernel(float* __restrict__ out) {
    int idx = blockIdx.x * blockDim.x + threadIdx.x;
    if (idx < N_NODES * DIM) out[idx] = g_node[idx];
}

extern "C" void kernel_launch(void* const* d_in, const int* in_sizes, int n_in,
                              void* d_out, int out_size) {
    const int* x = (const int*)d_in[0];
    const int* edge_attr = (const int*)d_in[1];
    const int* edge_index = (const int*)d_in[2];
    const float* atom_emb = (const float*)d_in[3];
    const float* bond_emb = (const float*)d_in[4];
    const float* eps = (const float*)d_in[5];
    const float* W1 = (const float*)d_in[6];
    const float* b1 = (const float*)d_in[7];
    const float* W2 = (const float*)d_in[8];
    const float* b2 = (const float*)d_in[9];
    const float* ln_g = (const float*)d_in[10];
    const float* ln_b = (const float*)d_in[11];
    const float* Wu1 = (const float*)d_in[12];
    const float* bu1 = (const float*)d_in[13];
    const float* ug = (const float*)d_in[14];
    const float* ub = (const float*)d_in[15];
    const float* Wu2 = (const float*)d_in[16];
    const float* bu2 = (const float*)d_in[17];
    float* out = (float*)d_out;

    float* g_edge_p = nullptr;
    cudaGetSymbolAddress((void**)&g_edge_p, g_edge);

    cudaFuncSetAttribute(node_mlp_kernel, cudaFuncAttributeMaxDynamicSharedMemorySize, 65536);
    cudaFuncSetAttribute(edge_layer_kernel, cudaFuncAttributeMaxDynamicSharedMemorySize, SMEM_EDGE);

    encode_node_kernel<<<(N_NODES * DIM + 255) / 256, 256>>>(x, atom_emb);
    encode_edge_kernel<<<(int)(((long)N_EDGES * DIM + 255) / 256), 256>>>(edge_attr, bond_emb);
    {
        int tot = NLAYERS * (DIM3 * DIM3 + DIM * DIM3);
        prep_weights_kernel<<<(tot + 255) / 256, 256>>>(Wu1, Wu2);
    }

    for (int l = 0; l < NLAYERS; l++) {
        zero_agg_kernel<<<(N_NODES * DIM + 255) / 256, 256>>>();
        scatter_kernel<<<(int)(((long)N_EDGES * 16 + 255) / 256), 256>>>(edge_index);
        node_mlp_kernel<<<444, 128, 65536>>>(
            W1 + (size_t)l * 64 * 128, b1 + l * 128,
            W2 + (size_t)l * 128 * 64, b2 + l * 64,
            ln_g + l * 64, ln_b + l * 64, eps, l);
        float* edge_out = (l == NLAYERS - 1) ? (out + (size_t)N_NODES * DIM) : g_edge_p;
        edge_layer_kernel<<<N_EDGES / 128, 256, SMEM_EDGE>>>(
            edge_index, bu1 + l * DIM3, ug + l * DIM3, ub + l * DIM3,
            bu2 + l * DIM, l, edge_out);
    }

    copy_node_kernel<<<(N_NODES * DIM + 255) / 256, 256>>>(out);
}